// round 17
// baseline (speedup 1.0000x reference)
#include <cuda_runtime.h>
#include <cuda_fp16.h>
#include <stdint.h>

#define BB 16
#define PP 8192
#define MM 128
#define KNN 16
#define DD 768
#define QQ (BB*MM)      // 2048 queries/tokens
#define RR (QQ*KNN)     // 32768 gathered rows

// ---------------- scratch (device globals; no allocation allowed) ----------------
__device__ float  g_cent[QQ*4];
__device__ int    g_knn[RR];
__device__ int    g_prog[BB];        // FPS centroid progress per batch
__device__ int    g_prog2[QQ];       // kNN done flag per (b,m)
__device__ int    g_cnt[544];        // chain counters: c1[256] c2[256] c3[16] c4[16]
#define C1 0
#define C2 256
#define C3 512
#define C4 528
__device__ __half g_bufA[(size_t)RR*768];
__device__ __half g_bufB[(size_t)RR*768];
__device__ __half g_pool[(size_t)QQ*DD];
__device__ __half g_h[(size_t)QQ*DD];
// transposed weights [N][K] (K-major so B operand is k-contiguous = "col" for mma)
#define OFF_W2T  0
#define OFF_W3T  (512*256)
#define OFF_W4T  (OFF_W3T + 768*512)
#define OFF_WA1T (OFF_W4T + 768*768)
#define OFF_WA2T (OFF_WA1T + 768*768)
__device__ __half g_wt[OFF_WA2T + 768*768];

// transpose ranges (element counts)
#define TN_W2  (256*512)
#define TN_W3  (512*768)
#define TN_W44 (768*768)
#define TE1 TN_W2
#define TE2 (TE1 + TN_W3)
#define TE3 (TE2 + TN_W44)
#define TE4 (TE3 + TN_W44)
#define TE5 (TE4 + TN_W44)
#define TE6 (TE5 + QQ)
#define NT_BLK ((TE6 + 1023) / 1024)             // transpose blocks (1024 thr each)
#define NG_BLK (RR / 32)                          // gather blocks (32 rows each) = 1024
#define FUSED_GRID (BB + NT_BLK + QQ + NG_BLK)    // fps + transpose + knn + gather

// ---------------- reset flags/counters (runs before fused kernel each replay) -----
__global__ void reset_prog()
{
    int t = threadIdx.x;
    if (t < BB) g_prog[t] = 0;
    if (t < 544) g_cnt[t] = 0;
    for (int i = t; i < QQ; i += 1024) g_prog2[i] = 0;
}

// ================= fused FPS + transpose + kNN + gather ===========================
__global__ __launch_bounds__(1024) void fused_front(
    const float* __restrict__ coords,
    float* __restrict__ cent_out2,
    const float* __restrict__ W2, const float* __restrict__ W3,
    const float* __restrict__ W4, const float* __restrict__ Wa1,
    const float* __restrict__ Wa2, float* __restrict__ masks,
    const float* __restrict__ feats,
    const float* __restrict__ W1, const float* __restrict__ b1)
{
    int bid = blockIdx.x;
    int tid = threadIdx.x;

    if (bid < BB) {
        // ---------------- FPS ----------------
        int b = bid;
        float px[8], py[8], pz[8], pw[8], dmin[8];
#pragma unroll
        for (int i = 0; i < 8; i++) {
            int p = tid + i * 1024;
            const float* c = coords + ((size_t)b * PP + p) * 5;
            px[i] = c[1]; py[i] = c[2]; pz[i] = c[3]; pw[i] = c[4];
            dmin[i] = 1e30f;
        }
        __shared__ float last[4];
        __shared__ unsigned long long red[32];
        __shared__ int cur_s;
        int cur = 0;
        for (int m = 0; m < MM; m++) {
            if (tid == (cur & 1023)) {
                int i = cur >> 10;
                last[0] = px[i]; last[1] = py[i]; last[2] = pz[i]; last[3] = pw[i];
                float* o  = g_cent + ((size_t)b * MM + m) * 4;
                o[0] = px[i]; o[1] = py[i]; o[2] = pz[i]; o[3] = pw[i];
                float* o2 = cent_out2 + ((size_t)b * MM + m) * 4;
                o2[0] = px[i]; o2[1] = py[i]; o2[2] = pz[i]; o2[3] = pw[i];
                __threadfence();
                ((volatile int*)g_prog)[b] = m + 1;      // release centroid m
            }
            __syncthreads();
            if (m == MM - 1) break;
            float lx = last[0], ly = last[1], lz = last[2], lw = last[3];
            float bestv = -1.0f;
            int   besti = 0;
#pragma unroll
            for (int i = 0; i < 8; i++) {
                float dx = __fsub_rn(px[i], lx);
                float dy = __fsub_rn(py[i], ly);
                float dz = __fsub_rn(pz[i], lz);
                float dw = __fsub_rn(pw[i], lw);
                float d = __fadd_rn(__fadd_rn(__fadd_rn(__fmul_rn(dx,dx), __fmul_rn(dy,dy)),
                                              __fmul_rn(dz,dz)), __fmul_rn(dw,dw));
                float dm = fminf(dmin[i], d);
                dmin[i] = dm;
                if (dm > bestv) { bestv = dm; besti = tid + i * 1024; }
            }
            unsigned long long best = ((unsigned long long)__float_as_uint(bestv) << 32)
                                    | (unsigned)(0x7FFFFFFF - besti);
            for (int off = 16; off; off >>= 1) {
                unsigned long long o = __shfl_down_sync(0xFFFFFFFFu, best, off);
                if (o > best) best = o;
            }
            if ((tid & 31) == 0) red[tid >> 5] = best;
            __syncthreads();
            if (tid < 32) {
                unsigned long long v = red[tid];
                for (int off = 16; off; off >>= 1) {
                    unsigned long long o = __shfl_down_sync(0xFFFFFFFFu, v, off);
                    if (o > v) v = o;
                }
                if (tid == 0) cur_s = 0x7FFFFFFF - (int)(v & 0xFFFFFFFFu);
            }
            __syncthreads();
            cur = cur_s;
        }
        return;
    }

    if (bid < BB + NT_BLK) {
        // ---------------- weight transpose + mask fill ----------------
        int i = (bid - BB) * 1024 + tid;
        const float* W; __half* dst; int N, K, j;
        if (i < TE1)      { j = i;       W = W2;  dst = g_wt + OFF_W2T;  K = 256; N = 512; }
        else if (i < TE2) { j = i - TE1; W = W3;  dst = g_wt + OFF_W3T;  K = 512; N = 768; }
        else if (i < TE3) { j = i - TE2; W = W4;  dst = g_wt + OFF_W4T;  K = 768; N = 768; }
        else if (i < TE4) { j = i - TE3; W = Wa1; dst = g_wt + OFF_WA1T; K = 768; N = 768; }
        else if (i < TE5) { j = i - TE4; W = Wa2; dst = g_wt + OFF_WA2T; K = 768; N = 768; }
        else if (i < TE6) { masks[i - TE5] = 1.0f; return; }
        else return;
        int k = j / N, n = j % N;
        dst[(size_t)n * K + k] = __float2half_rn(W[j]);
        return;
    }

    if (bid < BB + NT_BLK + QQ) {
        // ---------------- kNN (1024 threads, 8 pts/thread) ----------------
        extern __shared__ unsigned long long keys[];   // PP entries
        __shared__ unsigned long long red2[32];
        __shared__ unsigned long long win_s;
        int lin = bid - BB - NT_BLK;
        int m = lin >> 4;          // slow: early blocks need early centroids
        int b = lin & 15;

        if (tid == 0) {
            while (((volatile int*)g_prog)[b] <= m) __nanosleep(100);
            __threadfence();       // acquire
        }
        __syncthreads();

        const float* c = g_cent + ((size_t)b * MM + m) * 4;
        float c0 = __ldcg(c + 0), c1 = __ldcg(c + 1), c2 = __ldcg(c + 2), c3 = __ldcg(c + 3);
        float cen2 = __fadd_rn(__fadd_rn(__fadd_rn(__fmul_rn(c0,c0), __fmul_rn(c1,c1)),
                                         __fmul_rn(c2,c2)), __fmul_rn(c3,c3));
        unsigned long long mymin = ~0ull;
#pragma unroll
        for (int it = 0; it < PP / 1024; it++) {
            int p = tid + it * 1024;
            const float* q = coords + ((size_t)b * PP + p) * 5;
            float x0 = q[1], x1 = q[2], x2 = q[3], x3 = q[4];
            float pts2 = __fadd_rn(__fadd_rn(__fadd_rn(__fmul_rn(x0,x0), __fmul_rn(x1,x1)),
                                             __fmul_rn(x2,x2)), __fmul_rn(x3,x3));
            float dot  = __fadd_rn(__fadd_rn(__fadd_rn(__fmul_rn(c0,x0), __fmul_rn(c1,x1)),
                                             __fmul_rn(c2,x2)), __fmul_rn(c3,x3));
            float d2 = __fsub_rn(__fadd_rn(cen2, pts2), __fmul_rn(2.0f, dot));
            unsigned u = __float_as_uint(d2);
            u = (u & 0x80000000u) ? ~u : (u | 0x80000000u);   // order-preserving map
            unsigned long long key = ((unsigned long long)u << 32) | (unsigned)p;
            keys[p] = key;
            if (key < mymin) mymin = key;
        }
        __syncthreads();

        int* outp = g_knn + ((size_t)b * MM + m) * KNN;
        for (int k = 0; k < KNN; k++) {
            unsigned long long v = mymin;
            for (int off = 16; off; off >>= 1) {
                unsigned long long o = __shfl_down_sync(0xFFFFFFFFu, v, off);
                if (o < v) v = o;
            }
            if ((tid & 31) == 0) red2[tid >> 5] = v;
            __syncthreads();
            if (tid < 32) {
                unsigned long long w = red2[tid];
                for (int off = 16; off; off >>= 1) {
                    unsigned long long o = __shfl_down_sync(0xFFFFFFFFu, w, off);
                    if (o < w) w = o;
                }
                if (tid == 0) {
                    win_s = w;
                    outp[k] = (int)(w & 0xFFFFFFFFu);
                }
            }
            __syncthreads();
            if (mymin == win_s) {
                keys[(unsigned)(mymin & 0xFFFFFFFFu)] = ~0ull;
                unsigned long long nm = ~0ull;
#pragma unroll
                for (int it = 0; it < PP / 1024; it++) {
                    unsigned long long t = keys[tid + it * 1024];
                    if (t < nm) nm = t;
                }
                mymin = nm;
            }
        }
        if (tid == 0) {
            __threadfence();
            ((volatile int*)g_prog2)[b * MM + m] = 1;   // release kNN(b,m)
        }
        return;
    }

    // ---------------- gather + layer1 (6 -> 256, relu): 32 rows per block ----------
    {
        __shared__ float fs[32][6];
        int lin = bid - BB - NT_BLK - QQ;   // 0..NG_BLK-1
        int rowbase = lin * 32;
        int pair0 = lin * 2;                // (b,m) linear = row >> 4

        if (tid == 0) {
            while (((volatile int*)g_prog2)[pair0] == 0)     __nanosleep(100);
            while (((volatile int*)g_prog2)[pair0 + 1] == 0) __nanosleep(100);
            __threadfence();   // acquire
        }
        __syncthreads();

        if (tid < 192) {
            int r = tid / 6, cidx = tid % 6;
            int row = rowbase + r;
            int bidx = row >> 11;                       // row / (MM*KNN)
            int idx = g_knn[row];
            fs[r][cidx] = feats[((size_t)bidx * PP + idx) * 6 + cidx];
        }
        __syncthreads();

        int j = tid & 255;
        int rgrp = tid >> 8;       // 0..3
        float w[6];
#pragma unroll
        for (int t = 0; t < 6; t++) w[t] = W1[t * 256 + j];
        float bb = b1[j];
#pragma unroll
        for (int t8 = 0; t8 < 8; t8++) {
            int r = rgrp + 4 * t8;
            float acc = bb;
#pragma unroll
            for (int t = 0; t < 6; t++) acc = fmaf(fs[r][t], w[t], acc);
            g_bufA[(size_t)(rowbase + r) * 256 + j] = __float2half_rn(fmaxf(acc, 0.f));
        }
    }
}

// ================= fused GEMM chain: 5 layers in one launch ========================
// bid ranges: [0,1024) L1  [1024,2560) L2  [2560,4096) L3(pool)
//             [4096,4192) L4  [4192,4288) L5
// Cross-layer sync via g_cnt row-block counters. All A/B tile loads use cp.async.cg
// (L2-only) so produced data is never read through stale L1 lines.
#define SPAD 36                      // smem row stride in 32-bit words (=72 halves)
#define STG_MAT (128 * SPAD * 4)     // 18432 B per matrix per stage
#define STG_BYTES (2 * STG_MAT)      // 36864 B per stage (A + B)
#define NSTAGE 3
#define GSMEM (NSTAGE * STG_BYTES)   // 110592 B
#define CHAIN_GRID 4288

__device__ __forceinline__ void cp16(uint32_t saddr, const void* g) {
    asm volatile("cp.async.cg.shared.global [%0], [%1], 16;" :: "r"(saddr), "l"(g));
}
__device__ __forceinline__ void ldmx4(uint32_t& r0, uint32_t& r1, uint32_t& r2, uint32_t& r3,
                                      uint32_t saddr) {
    asm volatile("ldmatrix.sync.aligned.m8n8.x4.shared.b16 {%0,%1,%2,%3}, [%4];"
                 : "=r"(r0), "=r"(r1), "=r"(r2), "=r"(r3) : "r"(saddr));
}

__global__ __launch_bounds__(128, 2) void gemm_chain(
    __half* bufA, __half* bufB, const __half* wt,
    const float* b2, const float* b3, const float* b4,
    const float* ba1, const float* ba2,
    __half* pool, __half* h, float* tokens)
{
    extern __shared__ char dsm[];
    uint32_t sbase = (uint32_t)__cvta_generic_to_shared(dsm);
    int bid = blockIdx.x;
    int tid = threadIdx.x, wid = tid >> 5, lane = tid & 31;
    int gid = lane >> 2, tig = lane & 3;

    // ---- layer dispatch ----
    int l, lin;
    if      (bid < 1024) { l = 0; lin = bid; }
    else if (bid < 2560) { l = 1; lin = bid - 1024; }
    else if (bid < 4096) { l = 2; lin = bid - 2560; }
    else if (bid < 4192) { l = 3; lin = bid - 4096; }
    else                 { l = 4; lin = bid - 4192; }
    int tilesN = (l == 0) ? 4 : 6;
    int bx = lin % tilesN, by = lin / tilesN;

    const __half *A, *Bw; const float* bias; void* Cv;
    int N, K, RELU, POOLF, HALF;
    switch (l) {
    case 0:  A = bufA; Bw = wt + OFF_W2T;  bias = b2;  Cv = bufB;   N = 512; K = 256; RELU = 1; POOLF = 0; HALF = 1; break;
    case 1:  A = bufB; Bw = wt + OFF_W3T;  bias = b3;  Cv = bufA;   N = 768; K = 512; RELU = 1; POOLF = 0; HALF = 1; break;
    case 2:  A = bufA; Bw = wt + OFF_W4T;  bias = b4;  Cv = pool;   N = 768; K = 768; RELU = 0; POOLF = 1; HALF = 1; break;
    case 3:  A = pool; Bw = wt + OFF_WA1T; bias = ba1; Cv = h;      N = 768; K = 768; RELU = 1; POOLF = 0; HALF = 1; break;
    default: A = h;    Bw = wt + OFF_WA2T; bias = ba2; Cv = tokens; N = 768; K = 768; RELU = 0; POOLF = 0; HALF = 0; break;
    }

    // ---- wait on producers (row-block granularity) ----
    if (tid == 0) {
        volatile int* c = (volatile int*)g_cnt;
        if      (l == 1) { while (c[C1 + by] < 4)  __nanosleep(64); }
        else if (l == 2) { while (c[C2 + by] < 6)  __nanosleep(64); }
        else if (l == 3) { while (c[C3 + by] < 96) __nanosleep(64); }
        else if (l == 4) { while (c[C4 + by] < 6)  __nanosleep(64); }
        __threadfence();    // acquire
    }
    __syncthreads();

    int m_base = (wid & 1) * 64;
    int n_base = (wid >> 1) * 64;

    const __half* Ag = A  + (size_t)(by * 128) * K;
    const __half* Bg = Bw + (size_t)(bx * 128) * K;

    int srow[8], sq[8];
#pragma unroll
    for (int r = 0; r < 8; r++) {
        int id = tid + 128 * r;
        srow[r] = id >> 3;
        sq[r]   = id & 7;
    }

    int lr = lane & 7, mi = lane >> 3;
    int a_off[4], b_off[4];
#pragma unroll
    for (int mt = 0; mt < 4; mt++)
        a_off[mt] = (m_base + mt * 16 + lr + (mi & 1) * 8) * SPAD + (mi >> 1) * 4;
#pragma unroll
    for (int nt2 = 0; nt2 < 4; nt2++)
        b_off[nt2] = (n_base + nt2 * 16 + lr + (mi >> 1) * 8) * SPAD + (mi & 1) * 4;

    float acc[4][8][4];
#pragma unroll
    for (int mt = 0; mt < 4; mt++)
#pragma unroll
        for (int nt = 0; nt < 8; nt++)
#pragma unroll
            for (int j = 0; j < 4; j++) acc[mt][nt][j] = 0.f;

    int NC = K >> 6;

#pragma unroll
    for (int s = 0; s < 2; s++) {
        int kb = s << 6;
        uint32_t stb = sbase + s * STG_BYTES;
#pragma unroll
        for (int r = 0; r < 8; r++) {
            uint32_t doff = (uint32_t)(srow[r] * (SPAD * 4) + sq[r] * 16);
            cp16(stb + doff,           Ag + (size_t)srow[r] * K + kb + sq[r] * 8);
            cp16(stb + STG_MAT + doff, Bg + (size_t)srow[r] * K + kb + sq[r] * 8);
        }
        asm volatile("cp.async.commit_group;" ::: "memory");
    }

    for (int c = 0; c < NC; c++) {
        asm volatile("cp.async.wait_group 1;" ::: "memory");
        __syncthreads();

        if (c + 2 < NC) {
            int kb = (c + 2) << 6;
            uint32_t stb = sbase + ((c + 2) % NSTAGE) * STG_BYTES;
#pragma unroll
            for (int r = 0; r < 8; r++) {
                uint32_t doff = (uint32_t)(srow[r] * (SPAD * 4) + sq[r] * 16);
                cp16(stb + doff,           Ag + (size_t)srow[r] * K + kb + sq[r] * 8);
                cp16(stb + STG_MAT + doff, Bg + (size_t)srow[r] * K + kb + sq[r] * 8);
            }
        }
        asm volatile("cp.async.commit_group;" ::: "memory");

        uint32_t aBase = sbase + (c % NSTAGE) * STG_BYTES;
        uint32_t bBase = aBase + STG_MAT;

#pragma unroll
        for (int ks = 0; ks < 4; ks++) {
            int k0 = ks * 8;
            uint32_t af[4][4];
#pragma unroll
            for (int mt = 0; mt < 4; mt++)
                ldmx4(af[mt][0], af[mt][1], af[mt][2], af[mt][3],
                      aBase + (uint32_t)(a_off[mt] + k0) * 4);
#pragma unroll
            for (int nt2 = 0; nt2 < 4; nt2++) {
                uint32_t bf0, bf1, bf2, bf3;
                ldmx4(bf0, bf1, bf2, bf3, bBase + (uint32_t)(b_off[nt2] + k0) * 4);
#pragma unroll
                for (int mt = 0; mt < 4; mt++) {
                    asm volatile(
                        "mma.sync.aligned.m16n8k16.row.col.f32.f16.f16.f32 "
                        "{%0,%1,%2,%3}, {%4,%5,%6,%7}, {%8,%9}, {%0,%1,%2,%3};"
                        : "+f"(acc[mt][nt2*2][0]), "+f"(acc[mt][nt2*2][1]),
                          "+f"(acc[mt][nt2*2][2]), "+f"(acc[mt][nt2*2][3])
                        : "r"(af[mt][0]), "r"(af[mt][1]), "r"(af[mt][2]), "r"(af[mt][3]),
                          "r"(bf0), "r"(bf1));
                }
#pragma unroll
                for (int mt = 0; mt < 4; mt++) {
                    asm volatile(
                        "mma.sync.aligned.m16n8k16.row.col.f32.f16.f16.f32 "
                        "{%0,%1,%2,%3}, {%4,%5,%6,%7}, {%8,%9}, {%0,%1,%2,%3};"
                        : "+f"(acc[mt][nt2*2+1][0]), "+f"(acc[mt][nt2*2+1][1]),
                          "+f"(acc[mt][nt2*2+1][2]), "+f"(acc[mt][nt2*2+1][3])
                        : "r"(af[mt][0]), "r"(af[mt][1]), "r"(af[mt][2]), "r"(af[mt][3]),
                          "r"(bf2), "r"(bf3));
                }
            }
        }
    }

    // ---- epilogue (runtime flags; fragment ownership unchanged) ----
#pragma unroll
    for (int nt = 0; nt < 8; nt++) {
        int cg = bx * 128 + n_base + nt * 8 + 2 * tig;
        float bz0 = bias[cg], bz1 = bias[cg + 1];
#pragma unroll
        for (int mt = 0; mt < 4; mt++) {
            float v0 = acc[mt][nt][0] + bz0;
            float v1 = acc[mt][nt][1] + bz1;
            float v2 = acc[mt][nt][2] + bz0;
            float v3 = acc[mt][nt][3] + bz1;
            if (RELU) {
                v0 = fmaxf(v0, 0.f); v1 = fmaxf(v1, 0.f);
                v2 = fmaxf(v2, 0.f); v3 = fmaxf(v3, 0.f);
            }
            if (POOLF) {
                float m0 = fmaxf(v0, v2);
                float m1 = fmaxf(v1, v3);
#pragma unroll
                for (int off = 4; off <= 16; off <<= 1) {
                    m0 = fmaxf(m0, __shfl_xor_sync(0xFFFFFFFFu, m0, off));
                    m1 = fmaxf(m1, __shfl_xor_sync(0xFFFFFFFFu, m1, off));
                }
                if (gid == 0) {
                    int q = (by * 128 + m_base + mt * 16) >> 4;
                    __half* C = (__half*)Cv;
                    *(__half2*)(C + (size_t)q * N + cg) = __floats2half2_rn(m0, m1);
                }
            } else if (HALF) {
                int rg = by * 128 + m_base + mt * 16 + gid;
                __half* C = (__half*)Cv;
                *(__half2*)(C + (size_t)rg * N + cg)       = __floats2half2_rn(v0, v1);
                *(__half2*)(C + (size_t)(rg + 8) * N + cg) = __floats2half2_rn(v2, v3);
            } else {
                int rg = by * 128 + m_base + mt * 16 + gid;
                float* C = (float*)Cv;
                *(float2*)(C + (size_t)rg * N + cg)       = make_float2(v0, v1);
                *(float2*)(C + (size_t)(rg + 8) * N + cg) = make_float2(v2, v3);
            }
        }
    }

    // ---- signal consumers ----
    __threadfence();       // release this thread's stores
    __syncthreads();       // all threads' stores fenced
    if (tid == 0) {
        if      (l == 0) atomicAdd(&g_cnt[C1 + by], 1);
        else if (l == 1) atomicAdd(&g_cnt[C2 + by], 1);
        else if (l == 2) atomicAdd(&g_cnt[C3 + (by >> 4)], 1);
        else if (l == 3) atomicAdd(&g_cnt[C4 + by], 1);
    }
}

// ---------------- launcher ---------------------------------------------------------
extern "C" void kernel_launch(void* const* d_in, const int* in_sizes, int n_in,
                              void* d_out, int out_size)
{
    const float* coords = (const float*)d_in[0];
    const float* feats  = (const float*)d_in[1];
    const float* W1 = (const float*)d_in[2];  const float* b1 = (const float*)d_in[3];
    const float* W2 = (const float*)d_in[4];  const float* b2 = (const float*)d_in[5];
    const float* W3 = (const float*)d_in[6];  const float* b3 = (const float*)d_in[7];
    const float* W4 = (const float*)d_in[8];  const float* b4 = (const float*)d_in[9];
    const float* Wa1 = (const float*)d_in[10]; const float* ba1 = (const float*)d_in[11];
    const float* Wa2 = (const float*)d_in[12]; const float* ba2 = (const float*)d_in[13];

    float* out     = (float*)d_out;
    float* tokens  = out;                               // [QQ, DD]
    float* centout = out + (size_t)QQ * DD;             // [QQ, 4]
    float* masks   = centout + (size_t)QQ * 4;          // [QQ]

    __half *pA, *pB, *pPool, *pH, *pWt;
    cudaGetSymbolAddress((void**)&pA, g_bufA);
    cudaGetSymbolAddress((void**)&pB, g_bufB);
    cudaGetSymbolAddress((void**)&pPool, g_pool);
    cudaGetSymbolAddress((void**)&pH, g_h);
    cudaGetSymbolAddress((void**)&pWt, g_wt);

    // 1. reset progress flags + chain counters (every replay)
    reset_prog<<<1, 1024>>>();

    // 2. fused FPS + transpose/mask + kNN + gather (flag-pipelined)
    cudaFuncSetAttribute(fused_front, cudaFuncAttributeMaxDynamicSharedMemorySize, PP * 8);
    fused_front<<<FUSED_GRID, 1024, PP * 8>>>(coords, centout,
                                              W2, W3, W4, Wa1, Wa2, masks,
                                              feats, W1, b1);

    // 3. all 5 GEMM layers in one flag-chained launch
    cudaFuncSetAttribute(gemm_chain, cudaFuncAttributeMaxDynamicSharedMemorySize, GSMEM);
    gemm_chain<<<CHAIN_GRID, 128, GSMEM>>>(pA, pB, pWt,
                                           b2, b3, b4, ba1, ba2,
                                           pPool, pH, tokens);
}